// round 6
// baseline (speedup 1.0000x reference)
#include <cuda_runtime.h>
#include <cuda_fp16.h>
#include <math.h>

#define HIDDEN 256
#define NPTS   4096
#define KANCH  64
#define ND     400             // d-table rows: x in [0, 50), h = 1/8
#define NA     112             // a-table rows: x in [0, 14), h = 1/8
#define RPB    8               // rows per build block
#define INV_H  8.0f            // table rows per unit x
#define PPB    28              // points per main block
#define MAINT  256             // threads per main block

// -ln(10000)/256
#define NEG_LOG1E4_OVER_256 (-0.0359778921f)
// FACTOR_A = 180/(15*pi)
#define FACTOR_A 3.8197186342f

__device__ float g_WdT[HIDDEN * HIDDEN];
__device__ float g_WaT[HIDDEN * HIDDEN];
// Per row r, per channel quad t (t=0..63), channels 4t..4t+3:
//   .x = half2(v[4t],  v[4t+1])   .y = half2(dv[4t], dv[4t+1])
//   .z = half2(v[4t+2],v[4t+3])   .w = half2(dv[4t+2],dv[4t+3])
__device__ uint4 g_pd[ND * (HIDDEN / 4)];
__device__ uint4 g_pa[NA * (HIDDEN / 4)];

__device__ __forceinline__ __half2 as_h2(unsigned int v) {
    __half2 h;
    *reinterpret_cast<unsigned int*>(&h) = v;
    return h;
}
__device__ __forceinline__ unsigned int as_u32(__half2 h) {
    return *reinterpret_cast<unsigned int*>(&h);
}

// ---------------------------------------------------------------------------
// Transpose Wd, Wa (o-major -> h-major). grid (8,8,2), block (32,8)
// ---------------------------------------------------------------------------
__global__ void transpose_kernel(const float* __restrict__ Wd,
                                 const float* __restrict__ Wa) {
    __shared__ float tile[32][33];
    const float* src = blockIdx.z ? Wa : Wd;
    float*       dst = blockIdx.z ? g_WaT : g_WdT;
    int x = blockIdx.x * 32 + threadIdx.x;
    int y = blockIdx.y * 32 + threadIdx.y;
#pragma unroll
    for (int dy = 0; dy < 32; dy += 8)
        tile[threadIdx.y + dy][threadIdx.x] = src[(y + dy) * HIDDEN + x];
    __syncthreads();
    int xo = blockIdx.y * 32 + threadIdx.x;
    int yo = blockIdx.x * 32 + threadIdx.y;
#pragma unroll
    for (int dy = 0; dy < 32; dy += 8)
        dst[(yo + dy) * HIDDEN + xo] = tile[threadIdx.x][threadIdx.y + dy];
}

// ---------------------------------------------------------------------------
// Build half2-packed lookup tables. One block computes RPB rows (+1 overlap
// row for the delta). grid (ND+NA)/RPB = 64 blocks, 256 threads.
// ---------------------------------------------------------------------------
__global__ void build_kernel(const float* __restrict__ bd,
                             const float* __restrict__ ba) {
    __shared__ float emb[RPB + 1][HIDDEN];
    __shared__ float accs[RPB + 1][HIDDEN];
    const int b   = blockIdx.x;
    const int tid = threadIdx.x;
    const bool is_a = (b >= ND / RPB);
    const int row0  = is_a ? (b - ND / RPB) * RPB : b * RPB;
    const float* WT   = is_a ? g_WaT : g_WdT;
    const float* bias = is_a ? ba : bd;
    uint4* out        = is_a ? g_pa : g_pd;

    for (int e = tid; e < (RPB + 1) * 128; e += blockDim.x) {
        int rr = e >> 7;
        int i  = e & 127;
        float x = (float)(row0 + rr) * (1.0f / INV_H);
        float w = expf((float)(2 * i) * NEG_LOG1E4_OVER_256);
        float s, c;
        sincosf(x * w, &s, &c);
        emb[rr][2 * i]     = s;
        emb[rr][2 * i + 1] = c;
    }
    __syncthreads();

    const int o = tid;
    float acc[RPB + 1];
#pragma unroll
    for (int rr = 0; rr <= RPB; rr++) acc[rr] = 0.0f;
    for (int h = 0; h < HIDDEN; h++) {
        float w = __ldg(&WT[h * HIDDEN + o]);
#pragma unroll
        for (int rr = 0; rr <= RPB; rr++)
            acc[rr] = fmaf(emb[rr][h], w, acc[rr]);
    }
    float bo = __ldg(&bias[o]);
#pragma unroll
    for (int rr = 0; rr <= RPB; rr++) accs[rr][o] = acc[rr] + bo;
    __syncthreads();

    if (tid < 64) {
        const int t = tid;
#pragma unroll
        for (int rr = 0; rr < RPB; rr++) {
            float a0 = accs[rr][4 * t],     a1 = accs[rr][4 * t + 1];
            float a2 = accs[rr][4 * t + 2], a3 = accs[rr][4 * t + 3];
            float b0 = accs[rr + 1][4 * t],     b1 = accs[rr + 1][4 * t + 1];
            float b2 = accs[rr + 1][4 * t + 2], b3 = accs[rr + 1][4 * t + 3];
            uint4 pk;
            pk.x = as_u32(__floats2half2_rn(a0, a1));
            pk.y = as_u32(__floats2half2_rn(b0 - a0, b1 - a1));
            pk.z = as_u32(__floats2half2_rn(a2, a3));
            pk.w = as_u32(__floats2half2_rn(b2 - a2, b3 - a3));
            out[(row0 + rr) * 64 + t] = pk;
        }
    }
}

// ---------------------------------------------------------------------------
// Main pass: PPB points per 256-thread block.
//   smem: full a-table (112 KB) + per-(p,k) metadata (uint4 each).
//   d gathers stay global (LDG.128); a gathers become LDS.128.
// ---------------------------------------------------------------------------
__global__ void __launch_bounds__(MAINT)
main_kernel(const float* __restrict__ points,
            const float* __restrict__ anchors,
            float* __restrict__ out) {
    extern __shared__ uint4 smem[];
    uint4* s_atab = smem;                       // NA*64 = 7168 uint4
    uint4* s_meta = smem + NA * 64;             // PPB*64 uint4: {jd*64, ja*64, fd, fa}

    const int n0  = blockIdx.x * PPB;
    const int tid = threadIdx.x;

    // stage a-table into smem
#pragma unroll
    for (int i = tid; i < NA * 64; i += MAINT)
        s_atab[i] = __ldg(&g_pa[i]);

    // geometry: one (point, k) task per thread, strided
    for (int task = tid; task < PPB * KANCH; task += MAINT) {
        const int p = task >> 6;
        const int k = task & 63;
        int n = n0 + p;
        if (n >= NPTS) n = NPTS - 1;
        const float px = __ldg(&points[n * 3 + 0]);
        const float py = __ldg(&points[n * 3 + 1]);
        const float pz = __ldg(&points[n * 3 + 2]);
        const int k1 = (k + 1) & (KANCH - 1);
        const float ax = __ldg(&anchors[k * 3 + 0]);
        const float ay = __ldg(&anchors[k * 3 + 1]);
        const float az = __ldg(&anchors[k * 3 + 2]);
        const float bx = __ldg(&anchors[k1 * 3 + 0]);
        const float by = __ldg(&anchors[k1 * 3 + 1]);
        const float bz = __ldg(&anchors[k1 * 3 + 2]);

        float rx = px - ax, ry = py - ay, rz = pz - az;
        float ex = px - bx, ey = py - by, ez = pz - bz;

        float dist = sqrtf(rx * rx + ry * ry + rz * rz);
        float td = fminf(dist * (INV_H / 0.2f), (float)ND - 1.01f);
        int   jd = (int)td;
        float fd = td - (float)jd;

        float cx = ry * ez - rz * ey;
        float cy = rz * ex - rx * ez;
        float cz = rx * ey - ry * ex;
        float sv = sqrtf(cx * cx + cy * cy + cz * cz);
        float cv = rx * ex + ry * ey + rz * ez;
        float ang = atan2f(sv, cv);
        float ta = fminf(ang * (FACTOR_A * INV_H), (float)NA - 1.01f);
        ta = fmaxf(ta, 0.0f);
        int   ja = (int)ta;
        float fa = ta - (float)ja;

        s_meta[task] = make_uint4((unsigned)(jd * 64), (unsigned)(ja * 64),
                                  as_u32(__float2half2_rn(fd)),
                                  as_u32(__float2half2_rn(fa)));
    }
    __syncthreads();

    const int t = tid & 63;
    const int psub = tid >> 6;          // 4 points concurrently

#pragma unroll
    for (int pp = 0; pp < PPB; pp += 4) {
        const int p = pp + psub;
        const uint4* mrow = s_meta + p * KANCH;

        __half2 accd0 = __float2half2_rn(-60000.0f), accd1 = accd0;
        __half2 acca0 = accd0,                       acca1 = accd0;

#pragma unroll 8
        for (int k = 0; k < KANCH; k++) {
            uint4 m  = mrow[k];                   // broadcast LDS
            uint4 vd = __ldg(&g_pd[m.x + t]);     // global gather
            uint4 va = s_atab[m.y + t];           // smem gather
            __half2 fdh = as_h2(m.z), fah = as_h2(m.w);
            accd0 = __hmax2(accd0, __hfma2(fdh, as_h2(vd.y), as_h2(vd.x)));
            accd1 = __hmax2(accd1, __hfma2(fdh, as_h2(vd.w), as_h2(vd.z)));
            acca0 = __hmax2(acca0, __hfma2(fah, as_h2(va.y), as_h2(va.x)));
            acca1 = __hmax2(acca1, __hfma2(fah, as_h2(va.w), as_h2(va.z)));
        }

        const int n = n0 + p;
        if (n < NPTS) {
            float4 r;
            r.x = __low2float(accd0)  + __low2float(acca0);
            r.y = __high2float(accd0) + __high2float(acca0);
            r.z = __low2float(accd1)  + __low2float(acca1);
            r.w = __high2float(accd1) + __high2float(acca1);
            reinterpret_cast<float4*>(out)[n * 64 + t] = r;
        }
    }
}

// ---------------------------------------------------------------------------
extern "C" void kernel_launch(void* const* d_in, const int* in_sizes, int n_in,
                              void* d_out, int out_size) {
    const float* points  = (const float*)d_in[0];
    const float* anchors = (const float*)d_in[1];
    // d_in[2] = cor_score (unused by reference output)
    const float* Wa = (const float*)d_in[3];
    const float* ba = (const float*)d_in[4];
    const float* Wd = (const float*)d_in[5];
    const float* bd = (const float*)d_in[6];
    float* out = (float*)d_out;

    const int smem_bytes = (NA * 64 + PPB * KANCH) * (int)sizeof(uint4); // 143,360
    cudaFuncSetAttribute(main_kernel, cudaFuncAttributeMaxDynamicSharedMemorySize,
                         smem_bytes);

    transpose_kernel<<<dim3(8, 8, 2), dim3(32, 8)>>>(Wd, Wa);
    build_kernel<<<(ND + NA) / RPB, HIDDEN>>>(bd, ba);
    const int nblocks = (NPTS + PPB - 1) / PPB;   // 147
    main_kernel<<<nblocks, MAINT, smem_bytes>>>(points, anchors, out);
}

// round 9
// speedup vs baseline: 1.5712x; 1.5712x over previous
#include <cuda_runtime.h>
#include <cuda_fp16.h>
#include <math.h>

#define HIDDEN 256
#define NPTS   4096
#define KANCH  64
#define ND     400             // d-table rows: x in [0, 50), h = 1/8
#define NA     112             // a-table rows: x in [0, 14), h = 1/8
#define RPB    4               // rows per build block
#define INV_H  8.0f            // table rows per unit x
#define PPB    28              // points per main block
#define MAINT  512             // threads per main block
#define NGRP   (MAINT / 64)    // concurrent point-groups = 8

// -ln(10000)/256
#define NEG_LOG1E4_OVER_256 (-0.0359778921f)
// FACTOR_A = 180/(15*pi)
#define FACTOR_A 3.8197186342f

// Per row r, per channel quad t (t=0..63), channels 4t..4t+3:
//   .x = half2(v[4t],  v[4t+1])   .y = half2(dv[4t], dv[4t+1])
//   .z = half2(v[4t+2],v[4t+3])   .w = half2(dv[4t+2],dv[4t+3])
__device__ uint4 g_pd[ND * (HIDDEN / 4)];
__device__ uint4 g_pa[NA * (HIDDEN / 4)];

__device__ __forceinline__ __half2 as_h2(unsigned int v) {
    __half2 h;
    *reinterpret_cast<unsigned int*>(&h) = v;
    return h;
}
__device__ __forceinline__ unsigned int as_u32(__half2 h) {
    return *reinterpret_cast<unsigned int*>(&h);
}

// ---------------------------------------------------------------------------
// Build half2-packed lookup tables directly from row-major W (no transpose:
// thread o owns output channel o and reads its own W row via float4).
// One block computes RPB rows (+1 overlap row for the delta).
// grid = ND/RPB + NA/RPB = 100 + 28 = 128 blocks, 256 threads.
// ---------------------------------------------------------------------------
__global__ void build_kernel(const float* __restrict__ Wd,
                             const float* __restrict__ bd,
                             const float* __restrict__ Wa,
                             const float* __restrict__ ba) {
    __shared__ float emb[RPB + 1][HIDDEN];
    __shared__ float accs[RPB + 1][HIDDEN];
    const int b   = blockIdx.x;
    const int tid = threadIdx.x;
    const bool is_a = (b >= ND / RPB);
    const int row0  = is_a ? (b - ND / RPB) * RPB : b * RPB;
    const float* W    = is_a ? Wa : Wd;
    const float* bias = is_a ? ba : bd;
    uint4* out        = is_a ? g_pa : g_pd;

    // embeddings for RPB+1 consecutive x values
    for (int e = tid; e < (RPB + 1) * 128; e += blockDim.x) {
        int rr = e / 128;
        int i  = e & 127;
        float x = (float)(row0 + rr) * (1.0f / INV_H);
        float w = expf((float)(2 * i) * NEG_LOG1E4_OVER_256);
        float s, c;
        sincosf(x * w, &s, &c);
        emb[rr][2 * i]     = s;
        emb[rr][2 * i + 1] = c;
    }
    __syncthreads();

    const int o = tid;
    float acc[RPB + 1];
#pragma unroll
    for (int rr = 0; rr <= RPB; rr++) acc[rr] = 0.0f;
    const float4* wrow = reinterpret_cast<const float4*>(W + o * HIDDEN);
    for (int hq = 0; hq < HIDDEN / 4; hq++) {
        float4 w4 = __ldg(&wrow[hq]);
#pragma unroll
        for (int rr = 0; rr <= RPB; rr++) {
            acc[rr] = fmaf(emb[rr][4 * hq + 0], w4.x, acc[rr]);
            acc[rr] = fmaf(emb[rr][4 * hq + 1], w4.y, acc[rr]);
            acc[rr] = fmaf(emb[rr][4 * hq + 2], w4.z, acc[rr]);
            acc[rr] = fmaf(emb[rr][4 * hq + 3], w4.w, acc[rr]);
        }
    }
    float bo = __ldg(&bias[o]);
#pragma unroll
    for (int rr = 0; rr <= RPB; rr++) accs[rr][o] = acc[rr] + bo;
    __syncthreads();

    if (tid < 64) {
        const int t = tid;
#pragma unroll
        for (int rr = 0; rr < RPB; rr++) {
            float a0 = accs[rr][4 * t],     a1 = accs[rr][4 * t + 1];
            float a2 = accs[rr][4 * t + 2], a3 = accs[rr][4 * t + 3];
            float b0 = accs[rr + 1][4 * t],     b1 = accs[rr + 1][4 * t + 1];
            float b2 = accs[rr + 1][4 * t + 2], b3 = accs[rr + 1][4 * t + 3];
            uint4 pk;
            pk.x = as_u32(__floats2half2_rn(a0, a1));
            pk.y = as_u32(__floats2half2_rn(b0 - a0, b1 - a1));
            pk.z = as_u32(__floats2half2_rn(a2, a3));
            pk.w = as_u32(__floats2half2_rn(b2 - a2, b3 - a3));
            out[(row0 + rr) * 64 + t] = pk;
        }
    }
}

// ---------------------------------------------------------------------------
// Main pass: PPB points per 512-thread block (16 warps/SM, 1 block/SM).
//   smem: full a-table (112 KB) + per-(p,k) metadata.
//   d gathers stay global (LDG.128); a gathers are LDS.128.
//   Outer point loop NOT unrolled (I-cache); inner k-loop unrolled 8.
// ---------------------------------------------------------------------------
__global__ void __launch_bounds__(MAINT)
main_kernel(const float* __restrict__ points,
            const float* __restrict__ anchors,
            float* __restrict__ out) {
    extern __shared__ uint4 smem[];
    uint4* s_atab = smem;                       // NA*64 = 7168 uint4 (112 KB)
    uint4* s_meta = smem + NA * 64;             // PPB*64 uint4: {jd*64, ja*64, fd, fa}

    const int n0  = blockIdx.x * PPB;
    const int tid = threadIdx.x;

    // stage a-table into smem
    for (int i = tid; i < NA * 64; i += MAINT)
        s_atab[i] = __ldg(&g_pa[i]);

    // geometry: one (point, k) task per thread, strided
    for (int task = tid; task < PPB * KANCH; task += MAINT) {
        const int p = task >> 6;
        const int k = task & 63;
        int n = n0 + p;
        if (n >= NPTS) n = NPTS - 1;
        const float px = __ldg(&points[n * 3 + 0]);
        const float py = __ldg(&points[n * 3 + 1]);
        const float pz = __ldg(&points[n * 3 + 2]);
        const int k1 = (k + 1) & (KANCH - 1);
        const float ax = __ldg(&anchors[k * 3 + 0]);
        const float ay = __ldg(&anchors[k * 3 + 1]);
        const float az = __ldg(&anchors[k * 3 + 2]);
        const float bx = __ldg(&anchors[k1 * 3 + 0]);
        const float by = __ldg(&anchors[k1 * 3 + 1]);
        const float bz = __ldg(&anchors[k1 * 3 + 2]);

        float rx = px - ax, ry = py - ay, rz = pz - az;
        float ex = px - bx, ey = py - by, ez = pz - bz;

        float dist = sqrtf(rx * rx + ry * ry + rz * rz);
        float td = fminf(dist * (INV_H / 0.2f), (float)ND - 1.01f);
        int   jd = (int)td;
        float fd = td - (float)jd;

        float cx = ry * ez - rz * ey;
        float cy = rz * ex - rx * ez;
        float cz = rx * ey - ry * ex;
        float sv = sqrtf(cx * cx + cy * cy + cz * cz);
        float cv = rx * ex + ry * ey + rz * ez;
        float ang = atan2f(sv, cv);
        float ta = fminf(ang * (FACTOR_A * INV_H), (float)NA - 1.01f);
        ta = fmaxf(ta, 0.0f);
        int   ja = (int)ta;
        float fa = ta - (float)ja;

        s_meta[task] = make_uint4((unsigned)(jd * 64), (unsigned)(ja * 64),
                                  as_u32(__float2half2_rn(fd)),
                                  as_u32(__float2half2_rn(fa)));
    }
    __syncthreads();

    const int t    = tid & 63;
    const int psub = tid >> 6;          // 8 point-groups concurrently

#pragma unroll 1
    for (int pp = 0; pp < PPB; pp += NGRP) {
        const int p = pp + psub;
        if (p < PPB) {
            const uint4* mrow = s_meta + p * KANCH;

            __half2 accd0 = __float2half2_rn(-60000.0f), accd1 = accd0;
            __half2 acca0 = accd0,                       acca1 = accd0;

#pragma unroll 8
            for (int k = 0; k < KANCH; k++) {
                uint4 m  = mrow[k];                   // broadcast LDS
                uint4 vd = __ldg(&g_pd[m.x + t]);     // global gather
                uint4 va = s_atab[m.y + t];           // smem gather
                __half2 fdh = as_h2(m.z), fah = as_h2(m.w);
                accd0 = __hmax2(accd0, __hfma2(fdh, as_h2(vd.y), as_h2(vd.x)));
                accd1 = __hmax2(accd1, __hfma2(fdh, as_h2(vd.w), as_h2(vd.z)));
                acca0 = __hmax2(acca0, __hfma2(fah, as_h2(va.y), as_h2(va.x)));
                acca1 = __hmax2(acca1, __hfma2(fah, as_h2(va.w), as_h2(va.z)));
            }

            const int n = n0 + p;
            if (n < NPTS) {
                float4 r;
                r.x = __low2float(accd0)  + __low2float(acca0);
                r.y = __high2float(accd0) + __high2float(acca0);
                r.z = __low2float(accd1)  + __low2float(acca1);
                r.w = __high2float(accd1) + __high2float(acca1);
                reinterpret_cast<float4*>(out)[n * 64 + t] = r;
            }
        }
    }
}

// ---------------------------------------------------------------------------
extern "C" void kernel_launch(void* const* d_in, const int* in_sizes, int n_in,
                              void* d_out, int out_size) {
    const float* points  = (const float*)d_in[0];
    const float* anchors = (const float*)d_in[1];
    // d_in[2] = cor_score (unused by reference output)
    const float* Wa = (const float*)d_in[3];
    const float* ba = (const float*)d_in[4];
    const float* Wd = (const float*)d_in[5];
    const float* bd = (const float*)d_in[6];
    float* out = (float*)d_out;

    const int smem_bytes = (NA * 64 + PPB * KANCH) * (int)sizeof(uint4);
    cudaFuncSetAttribute(main_kernel, cudaFuncAttributeMaxDynamicSharedMemorySize,
                         smem_bytes);

    build_kernel<<<ND / RPB + NA / RPB, HIDDEN>>>(Wd, bd, Wa, ba);
    const int nblocks = (NPTS + PPB - 1) / PPB;   // 147
    main_kernel<<<nblocks, MAINT, smem_bytes>>>(points, anchors, out);
}

// round 10
// speedup vs baseline: 1.8223x; 1.1599x over previous
#include <cuda_runtime.h>
#include <cuda_fp16.h>
#include <math.h>

#define HIDDEN 256
#define NPTS   4096
#define KANCH  64
#define ND     400             // d-table rows: x in [0, 50), h = 1/8
#define NA     112             // a-table rows: x in [0, 14), h = 1/8
#define RPB    4               // rows per build block
#define INV_H  8.0f            // table rows per unit x
#define PPB    28              // points per main block
#define MAINT  1024            // threads per main block (32 warps/SM)
#define NGRP   (MAINT / 64)    // concurrent point-groups = 16

// -ln(10000)/256
#define NEG_LOG1E4_OVER_256 (-0.0359778921f)
// FACTOR_A = 180/(15*pi)
#define FACTOR_A 3.8197186342f

// Per row r, per channel quad t (t=0..63), channels 4t..4t+3:
//   .x = half2(v[4t],  v[4t+1])   .y = half2(dv[4t], dv[4t+1])
//   .z = half2(v[4t+2],v[4t+3])   .w = half2(dv[4t+2],dv[4t+3])
__device__ uint4 g_pd[ND * (HIDDEN / 4)];
__device__ uint4 g_pa[NA * (HIDDEN / 4)];

__device__ __forceinline__ __half2 as_h2(unsigned int v) {
    __half2 h;
    *reinterpret_cast<unsigned int*>(&h) = v;
    return h;
}
__device__ __forceinline__ unsigned int as_u32(__half2 h) {
    return *reinterpret_cast<unsigned int*>(&h);
}

// ---------------------------------------------------------------------------
// Build half2-packed lookup tables directly from row-major W (thread o owns
// output channel o, reads its own W row via float4).
// One block computes RPB rows (+1 overlap row for the delta).
// grid = ND/RPB + NA/RPB = 100 + 28 = 128 blocks, 256 threads.
// ---------------------------------------------------------------------------
__global__ void build_kernel(const float* __restrict__ Wd,
                             const float* __restrict__ bd,
                             const float* __restrict__ Wa,
                             const float* __restrict__ ba) {
    __shared__ float emb[RPB + 1][HIDDEN];
    __shared__ float accs[RPB + 1][HIDDEN];
    const int b   = blockIdx.x;
    const int tid = threadIdx.x;
    const bool is_a = (b >= ND / RPB);
    const int row0  = is_a ? (b - ND / RPB) * RPB : b * RPB;
    const float* W    = is_a ? Wa : Wd;
    const float* bias = is_a ? ba : bd;
    uint4* out        = is_a ? g_pa : g_pd;

    for (int e = tid; e < (RPB + 1) * 128; e += blockDim.x) {
        int rr = e / 128;
        int i  = e & 127;
        float x = (float)(row0 + rr) * (1.0f / INV_H);
        float w = expf((float)(2 * i) * NEG_LOG1E4_OVER_256);
        float s, c;
        sincosf(x * w, &s, &c);
        emb[rr][2 * i]     = s;
        emb[rr][2 * i + 1] = c;
    }
    __syncthreads();

    const int o = tid;
    float acc[RPB + 1];
#pragma unroll
    for (int rr = 0; rr <= RPB; rr++) acc[rr] = 0.0f;
    const float4* wrow = reinterpret_cast<const float4*>(W + o * HIDDEN);
    for (int hq = 0; hq < HIDDEN / 4; hq++) {
        float4 w4 = __ldg(&wrow[hq]);
#pragma unroll
        for (int rr = 0; rr <= RPB; rr++) {
            acc[rr] = fmaf(emb[rr][4 * hq + 0], w4.x, acc[rr]);
            acc[rr] = fmaf(emb[rr][4 * hq + 1], w4.y, acc[rr]);
            acc[rr] = fmaf(emb[rr][4 * hq + 2], w4.z, acc[rr]);
            acc[rr] = fmaf(emb[rr][4 * hq + 3], w4.w, acc[rr]);
        }
    }
    float bo = __ldg(&bias[o]);
#pragma unroll
    for (int rr = 0; rr <= RPB; rr++) accs[rr][o] = acc[rr] + bo;
    __syncthreads();

    if (tid < 64) {
        const int t = tid;
#pragma unroll
        for (int rr = 0; rr < RPB; rr++) {
            float a0 = accs[rr][4 * t],     a1 = accs[rr][4 * t + 1];
            float a2 = accs[rr][4 * t + 2], a3 = accs[rr][4 * t + 3];
            float b0 = accs[rr + 1][4 * t],     b1 = accs[rr + 1][4 * t + 1];
            float b2 = accs[rr + 1][4 * t + 2], b3 = accs[rr + 1][4 * t + 3];
            uint4 pk;
            pk.x = as_u32(__floats2half2_rn(a0, a1));
            pk.y = as_u32(__floats2half2_rn(b0 - a0, b1 - a1));
            pk.z = as_u32(__floats2half2_rn(a2, a3));
            pk.w = as_u32(__floats2half2_rn(b2 - a2, b3 - a3));
            out[(row0 + rr) * 64 + t] = pk;
        }
    }
}

// ---------------------------------------------------------------------------
// Main pass: PPB points per 1024-thread block (32 warps/SM, 1 block/SM).
//   smem: full a-table (112 KB) + per-(p,k) metadata.
//   d gathers stay global (LDG.128); a gathers are LDS.128.
// ---------------------------------------------------------------------------
__global__ void __launch_bounds__(MAINT)
main_kernel(const float* __restrict__ points,
            const float* __restrict__ anchors,
            float* __restrict__ out) {
    extern __shared__ uint4 smem[];
    uint4* s_atab = smem;                       // NA*64 = 7168 uint4 (112 KB)
    uint4* s_meta = smem + NA * 64;             // PPB*64 uint4: {jd*64, ja*64, fd, fa}

    const int n0  = blockIdx.x * PPB;
    const int tid = threadIdx.x;

    // stage a-table into smem
    for (int i = tid; i < NA * 64; i += MAINT)
        s_atab[i] = __ldg(&g_pa[i]);

    // geometry: one (point, k) task per thread, strided
    for (int task = tid; task < PPB * KANCH; task += MAINT) {
        const int p = task >> 6;
        const int k = task & 63;
        int n = n0 + p;
        if (n >= NPTS) n = NPTS - 1;
        const float px = __ldg(&points[n * 3 + 0]);
        const float py = __ldg(&points[n * 3 + 1]);
        const float pz = __ldg(&points[n * 3 + 2]);
        const int k1 = (k + 1) & (KANCH - 1);
        const float ax = __ldg(&anchors[k * 3 + 0]);
        const float ay = __ldg(&anchors[k * 3 + 1]);
        const float az = __ldg(&anchors[k * 3 + 2]);
        const float bx = __ldg(&anchors[k1 * 3 + 0]);
        const float by = __ldg(&anchors[k1 * 3 + 1]);
        const float bz = __ldg(&anchors[k1 * 3 + 2]);

        float rx = px - ax, ry = py - ay, rz = pz - az;
        float ex = px - bx, ey = py - by, ez = pz - bz;

        float dist = sqrtf(rx * rx + ry * ry + rz * rz);
        float td = fminf(dist * (INV_H / 0.2f), (float)ND - 1.01f);
        int   jd = (int)td;
        float fd = td - (float)jd;

        float cx = ry * ez - rz * ey;
        float cy = rz * ex - rx * ez;
        float cz = rx * ey - ry * ex;
        float sv = sqrtf(cx * cx + cy * cy + cz * cz);
        float cv = rx * ex + ry * ey + rz * ez;
        float ang = atan2f(sv, cv);
        float ta = fminf(ang * (FACTOR_A * INV_H), (float)NA - 1.01f);
        ta = fmaxf(ta, 0.0f);
        int   ja = (int)ta;
        float fa = ta - (float)ja;

        s_meta[task] = make_uint4((unsigned)(jd * 64), (unsigned)(ja * 64),
                                  as_u32(__float2half2_rn(fd)),
                                  as_u32(__float2half2_rn(fa)));
    }
    __syncthreads();

    const int t    = tid & 63;
    const int psub = tid >> 6;          // 16 point-groups concurrently

#pragma unroll 1
    for (int pp = 0; pp < PPB; pp += NGRP) {
        const int p = pp + psub;
        if (p < PPB) {
            const uint4* mrow = s_meta + p * KANCH;

            __half2 accd0 = __float2half2_rn(-60000.0f), accd1 = accd0;
            __half2 acca0 = accd0,                       acca1 = accd0;

#pragma unroll 8
            for (int k = 0; k < KANCH; k++) {
                uint4 m  = mrow[k];                   // broadcast LDS
                uint4 vd = __ldg(&g_pd[m.x + t]);     // global gather
                uint4 va = s_atab[m.y + t];           // smem gather
                __half2 fdh = as_h2(m.z), fah = as_h2(m.w);
                accd0 = __hmax2(accd0, __hfma2(fdh, as_h2(vd.y), as_h2(vd.x)));
                accd1 = __hmax2(accd1, __hfma2(fdh, as_h2(vd.w), as_h2(vd.z)));
                acca0 = __hmax2(acca0, __hfma2(fah, as_h2(va.y), as_h2(va.x)));
                acca1 = __hmax2(acca1, __hfma2(fah, as_h2(va.w), as_h2(va.z)));
            }

            const int n = n0 + p;
            if (n < NPTS) {
                float4 r;
                r.x = __low2float(accd0)  + __low2float(acca0);
                r.y = __high2float(accd0) + __high2float(acca0);
                r.z = __low2float(accd1)  + __low2float(acca1);
                r.w = __high2float(accd1) + __high2float(acca1);
                reinterpret_cast<float4*>(out)[n * 64 + t] = r;
            }
        }
    }
}

// ---------------------------------------------------------------------------
extern "C" void kernel_launch(void* const* d_in, const int* in_sizes, int n_in,
                              void* d_out, int out_size) {
    const float* points  = (const float*)d_in[0];
    const float* anchors = (const float*)d_in[1];
    // d_in[2] = cor_score (unused by reference output)
    const float* Wa = (const float*)d_in[3];
    const float* ba = (const float*)d_in[4];
    const float* Wd = (const float*)d_in[5];
    const float* bd = (const float*)d_in[6];
    float* out = (float*)d_out;

    const int smem_bytes = (NA * 64 + PPB * KANCH) * (int)sizeof(uint4);
    cudaFuncSetAttribute(main_kernel, cudaFuncAttributeMaxDynamicSharedMemorySize,
                         smem_bytes);

    build_kernel<<<ND / RPB + NA / RPB, HIDDEN>>>(Wd, bd, Wa, ba);
    const int nblocks = (NPTS + PPB - 1) / PPB;   // 147
    main_kernel<<<nblocks, MAINT, smem_bytes>>>(points, anchors, out);
}

// round 14
// speedup vs baseline: 1.9846x; 1.0891x over previous
#include <cuda_runtime.h>
#include <cuda_fp16.h>
#include <math.h>

#define HIDDEN 256
#define NPTS   4096
#define KANCH  64
#define ND     400             // d-table rows: x in [0, 50), h = 1/8
#define NA     112             // a-table rows: x in [0, 14), h = 1/8
#define RPB    4               // rows per build block
#define INV_H  8.0f            // table rows per unit x
#define PPB    28              // points per main block
#define MAINT  1024            // threads per main block (32 warps/SM)
#define NGRP   (MAINT / 64)    // concurrent point-groups = 16

// -ln(10000)/256
#define NEG_LOG1E4_OVER_256 (-0.0359778921f)
// FACTOR_A = 180/(15*pi)
#define FACTOR_A 3.8197186342f

// Per row r, per channel quad t (t=0..63), channels 4t..4t+3:
//   .x = half2(v[4t],  v[4t+1])   .y = half2(dv[4t], dv[4t+1])
//   .z = half2(v[4t+2],v[4t+3])   .w = half2(dv[4t+2],dv[4t+3])
__device__ uint4 g_pd[ND * (HIDDEN / 4)];
__device__ uint4 g_pa[NA * (HIDDEN / 4)];

__device__ __forceinline__ __half2 as_h2(unsigned int v) {
    __half2 h;
    *reinterpret_cast<unsigned int*>(&h) = v;
    return h;
}
__device__ __forceinline__ unsigned int as_u32(__half2 h) {
    return *reinterpret_cast<unsigned int*>(&h);
}

// ---------------------------------------------------------------------------
// Build half2-packed lookup tables directly from row-major W (thread o owns
// output channel o, reads its own W row via float4).
// grid = ND/RPB + NA/RPB = 100 + 28 = 128 blocks, 256 threads.
// ---------------------------------------------------------------------------
__global__ void build_kernel(const float* __restrict__ Wd,
                             const float* __restrict__ bd,
                             const float* __restrict__ Wa,
                             const float* __restrict__ ba) {
    __shared__ float emb[RPB + 1][HIDDEN];
    __shared__ float accs[RPB + 1][HIDDEN];
    const int b   = blockIdx.x;
    const int tid = threadIdx.x;
    const bool is_a = (b >= ND / RPB);
    const int row0  = is_a ? (b - ND / RPB) * RPB : b * RPB;
    const float* W    = is_a ? Wa : Wd;
    const float* bias = is_a ? ba : bd;
    uint4* out        = is_a ? g_pa : g_pd;

    for (int e = tid; e < (RPB + 1) * 128; e += blockDim.x) {
        int rr = e / 128;
        int i  = e & 127;
        float x = (float)(row0 + rr) * (1.0f / INV_H);
        float w = expf((float)(2 * i) * NEG_LOG1E4_OVER_256);
        float s, c;
        sincosf(x * w, &s, &c);
        emb[rr][2 * i]     = s;
        emb[rr][2 * i + 1] = c;
    }
    __syncthreads();

    const int o = tid;
    float acc0[RPB + 1], acc1[RPB + 1];
#pragma unroll
    for (int rr = 0; rr <= RPB; rr++) { acc0[rr] = 0.0f; acc1[rr] = 0.0f; }
    const float4* wrow = reinterpret_cast<const float4*>(W + o * HIDDEN);
    // 2-wide unroll with dual accumulators: two independent LDG.128 in flight
    for (int hq = 0; hq < HIDDEN / 4; hq += 2) {
        float4 w4a = __ldg(&wrow[hq]);
        float4 w4b = __ldg(&wrow[hq + 1]);
#pragma unroll
        for (int rr = 0; rr <= RPB; rr++) {
            acc0[rr] = fmaf(emb[rr][4 * hq + 0], w4a.x, acc0[rr]);
            acc0[rr] = fmaf(emb[rr][4 * hq + 1], w4a.y, acc0[rr]);
            acc0[rr] = fmaf(emb[rr][4 * hq + 2], w4a.z, acc0[rr]);
            acc0[rr] = fmaf(emb[rr][4 * hq + 3], w4a.w, acc0[rr]);
            acc1[rr] = fmaf(emb[rr][4 * hq + 4], w4b.x, acc1[rr]);
            acc1[rr] = fmaf(emb[rr][4 * hq + 5], w4b.y, acc1[rr]);
            acc1[rr] = fmaf(emb[rr][4 * hq + 6], w4b.z, acc1[rr]);
            acc1[rr] = fmaf(emb[rr][4 * hq + 7], w4b.w, acc1[rr]);
        }
    }
    float bo = __ldg(&bias[o]);
#pragma unroll
    for (int rr = 0; rr <= RPB; rr++) accs[rr][o] = acc0[rr] + acc1[rr] + bo;
    __syncthreads();

    if (tid < 64) {
        const int t = tid;
#pragma unroll
        for (int rr = 0; rr < RPB; rr++) {
            float a0 = accs[rr][4 * t],     a1 = accs[rr][4 * t + 1];
            float a2 = accs[rr][4 * t + 2], a3 = accs[rr][4 * t + 3];
            float b0 = accs[rr + 1][4 * t],     b1 = accs[rr + 1][4 * t + 1];
            float b2 = accs[rr + 1][4 * t + 2], b3 = accs[rr + 1][4 * t + 3];
            uint4 pk;
            pk.x = as_u32(__floats2half2_rn(a0, a1));
            pk.y = as_u32(__floats2half2_rn(b0 - a0, b1 - a1));
            pk.z = as_u32(__floats2half2_rn(a2, a3));
            pk.w = as_u32(__floats2half2_rn(b2 - a2, b3 - a3));
            out[(row0 + rr) * 64 + t] = pk;
        }
    }
}

// ---------------------------------------------------------------------------
// Main pass: PPB points per 1024-thread block (32 warps/SM, 1 block/SM).
//   smem: full a-table (112 KB) + packed per-(p,k) metadata (uint2).
//   k-loop processes 4 anchors per iteration with front-batched loads (MLP=4).
// ---------------------------------------------------------------------------
__global__ void __launch_bounds__(MAINT)
main_kernel(const float* __restrict__ points,
            const float* __restrict__ anchors,
            float* __restrict__ out) {
    extern __shared__ uint4 smem[];
    uint4* s_atab = smem;                                    // NA*64 uint4 (112 KB)
    uint2* s_meta = reinterpret_cast<uint2*>(smem + NA * 64); // PPB*64 uint2

    const int n0  = blockIdx.x * PPB;
    const int tid = threadIdx.x;

    // stage a-table into smem
    for (int i = tid; i < NA * 64; i += MAINT)
        s_atab[i] = __ldg(&g_pa[i]);

    // geometry: one (point, k) task per thread, strided
    for (int task = tid; task < PPB * KANCH; task += MAINT) {
        const int p = task >> 6;
        const int k = task & 63;
        int n = n0 + p;
        if (n >= NPTS) n = NPTS - 1;
        const float px = __ldg(&points[n * 3 + 0]);
        const float py = __ldg(&points[n * 3 + 1]);
        const float pz = __ldg(&points[n * 3 + 2]);
        const int k1 = (k + 1) & (KANCH - 1);
        const float ax = __ldg(&anchors[k * 3 + 0]);
        const float ay = __ldg(&anchors[k * 3 + 1]);
        const float az = __ldg(&anchors[k * 3 + 2]);
        const float bx = __ldg(&anchors[k1 * 3 + 0]);
        const float by = __ldg(&anchors[k1 * 3 + 1]);
        const float bz = __ldg(&anchors[k1 * 3 + 2]);

        float rx = px - ax, ry = py - ay, rz = pz - az;
        float ex = px - bx, ey = py - by, ez = pz - bz;

        float dist = sqrtf(rx * rx + ry * ry + rz * rz);
        float td = fminf(dist * (INV_H / 0.2f), (float)ND - 1.01f);
        int   jd = (int)td;
        float fd = td - (float)jd;

        float cx = ry * ez - rz * ey;
        float cy = rz * ex - rx * ez;
        float cz = rx * ey - ry * ex;
        float sv = sqrtf(cx * cx + cy * cy + cz * cz);
        float cv = rx * ex + ry * ey + rz * ez;
        float ang = atan2f(sv, cv);
        float ta = fminf(ang * (FACTOR_A * INV_H), (float)NA - 1.01f);
        ta = fmaxf(ta, 0.0f);
        int   ja = (int)ta;
        float fa = ta - (float)ja;

        // pack: offsets (jd*64 | ja*64<<16) and fracs (fd,fa) as half2
        unsigned off = (unsigned)(jd * 64) | ((unsigned)(ja * 64) << 16);
        s_meta[task] = make_uint2(off, as_u32(__floats2half2_rn(fd, fa)));
    }
    __syncthreads();

    const int t    = tid & 63;
    const int psub = tid >> 6;          // 16 point-groups concurrently

#pragma unroll 1
    for (int pp = 0; pp < PPB; pp += NGRP) {
        const int p = pp + psub;
        if (p < PPB) {
            const uint2* mrow = s_meta + p * KANCH;

            __half2 accd0 = __float2half2_rn(-60000.0f), accd1 = accd0;
            __half2 acca0 = accd0,                       acca1 = accd0;

#pragma unroll 1
            for (int k0 = 0; k0 < KANCH; k0 += 4) {
                uint2 m0 = mrow[k0 + 0];
                uint2 m1 = mrow[k0 + 1];
                uint2 m2 = mrow[k0 + 2];
                uint2 m3 = mrow[k0 + 3];
                // batch the 4 global gathers (MLP=4)
                uint4 vd0 = __ldg(&g_pd[(m0.x & 0xFFFFu) + t]);
                uint4 vd1 = __ldg(&g_pd[(m1.x & 0xFFFFu) + t]);
                uint4 vd2 = __ldg(&g_pd[(m2.x & 0xFFFFu) + t]);
                uint4 vd3 = __ldg(&g_pd[(m3.x & 0xFFFFu) + t]);
                // batch the 4 smem gathers
                uint4 va0 = s_atab[(m0.x >> 16) + t];
                uint4 va1 = s_atab[(m1.x >> 16) + t];
                uint4 va2 = s_atab[(m2.x >> 16) + t];
                uint4 va3 = s_atab[(m3.x >> 16) + t];

                __half2 f0 = as_h2(m0.y), f1 = as_h2(m1.y);
                __half2 f2 = as_h2(m2.y), f3 = as_h2(m3.y);
                __half2 fd0 = __half2half2(__low2half(f0)),  fa0 = __half2half2(__high2half(f0));
                __half2 fd1 = __half2half2(__low2half(f1)),  fa1 = __half2half2(__high2half(f1));
                __half2 fd2 = __half2half2(__low2half(f2)),  fa2 = __half2half2(__high2half(f2));
                __half2 fd3 = __half2half2(__low2half(f3)),  fa3 = __half2half2(__high2half(f3));

                accd0 = __hmax2(accd0, __hfma2(fd0, as_h2(vd0.y), as_h2(vd0.x)));
                accd1 = __hmax2(accd1, __hfma2(fd0, as_h2(vd0.w), as_h2(vd0.z)));
                acca0 = __hmax2(acca0, __hfma2(fa0, as_h2(va0.y), as_h2(va0.x)));
                acca1 = __hmax2(acca1, __hfma2(fa0, as_h2(va0.w), as_h2(va0.z)));

                accd0 = __hmax2(accd0, __hfma2(fd1, as_h2(vd1.y), as_h2(vd1.x)));
                accd1 = __hmax2(accd1, __hfma2(fd1, as_h2(vd1.w), as_h2(vd1.z)));
                acca0 = __hmax2(acca0, __hfma2(fa1, as_h2(va1.y), as_h2(va1.x)));
                acca1 = __hmax2(acca1, __hfma2(fa1, as_h2(va1.w), as_h2(va1.z)));

                accd0 = __hmax2(accd0, __hfma2(fd2, as_h2(vd2.y), as_h2(vd2.x)));
                accd1 = __hmax2(accd1, __hfma2(fd2, as_h2(vd2.w), as_h2(vd2.z)));
                acca0 = __hmax2(acca0, __hfma2(fa2, as_h2(va2.y), as_h2(va2.x)));
                acca1 = __hmax2(acca1, __hfma2(fa2, as_h2(va2.w), as_h2(va2.z)));

                accd0 = __hmax2(accd0, __hfma2(fd3, as_h2(vd3.y), as_h2(vd3.x)));
                accd1 = __hmax2(accd1, __hfma2(fd3, as_h2(vd3.w), as_h2(vd3.z)));
                acca0 = __hmax2(acca0, __hfma2(fa3, as_h2(va3.y), as_h2(va3.x)));
                acca1 = __hmax2(acca1, __hfma2(fa3, as_h2(va3.w), as_h2(va3.z)));
            }

            const int n = n0 + p;
            if (n < NPTS) {
                float4 r;
                r.x = __low2float(accd0)  + __low2float(acca0);
                r.y = __high2float(accd0) + __high2float(acca0);
                r.z = __low2float(accd1)  + __low2float(acca1);
                r.w = __high2float(accd1) + __high2float(acca1);
                reinterpret_cast<float4*>(out)[n * 64 + t] = r;
            }
        }
    }
}

// ---------------------------------------------------------------------------
extern "C" void kernel_launch(void* const* d_in, const int* in_sizes, int n_in,
                              void* d_out, int out_size) {
    const float* points  = (const float*)d_in[0];
    const float* anchors = (const float*)d_in[1];
    // d_in[2] = cor_score (unused by reference output)
    const float* Wa = (const float*)d_in[3];
    const float* ba = (const float*)d_in[4];
    const float* Wd = (const float*)d_in[5];
    const float* bd = (const float*)d_in[6];
    float* out = (float*)d_out;

    const int smem_bytes = NA * 64 * (int)sizeof(uint4)
                         + PPB * KANCH * (int)sizeof(uint2);
    cudaFuncSetAttribute(main_kernel, cudaFuncAttributeMaxDynamicSharedMemorySize,
                         smem_bytes);

    build_kernel<<<ND / RPB + NA / RPB, HIDDEN>>>(Wd, bd, Wa, ba);
    const int nblocks = (NPTS + PPB - 1) / PPB;   // 147
    main_kernel<<<nblocks, MAINT, smem_bytes>>>(points, anchors, out);
}